// round 15
// baseline (speedup 1.0000x reference)
#include <cuda_runtime.h>

typedef unsigned long long u64t;

// ---- packed f32x2 helpers (sm_103a) ----
__device__ __forceinline__ u64t pack2(float x, float y){
    u64t r; asm("mov.b64 %0,{%1,%2};" : "=l"(r) : "f"(x), "f"(y)); return r;
}
__device__ __forceinline__ float2 unpack2(u64t a){
    float2 r; asm("mov.b64 {%0,%1},%2;" : "=f"(r.x), "=f"(r.y) : "l"(a)); return r;
}
__device__ __forceinline__ u64t fma2_(u64t a, u64t b, u64t c){
    u64t d; asm("fma.rn.f32x2 %0,%1,%2,%3;" : "=l"(d) : "l"(a), "l"(b), "l"(c)); return d;
}
__device__ __forceinline__ u64t mul2_(u64t a, u64t b){
    u64t d; asm("mul.rn.f32x2 %0,%1,%2;" : "=l"(d) : "l"(a), "l"(b)); return d;
}

#define NB     32                 // batches
#define NI     4096               // input capsules
#define NO     32                 // output capsules
#define NPAIR  (NI / 2)           // 2048 capsule pairs
#define CI     64                 // i per chunk
#define CP     (CI / 2)           // 32 pairs per chunk
#define NCHUNK (NI / CI)          // 64 chunks (= partial slabs)
#define EL     (NB * NO * 16)     // 16384 output elements
#define PSLAB  EL                 // floats per partial slab

// scratch (static device globals — no allocations)
__device__ __align__(16) u64t  g_wt2[NPAIR * 16 * NO];   // W i-paired: [IP][k][o], 8 MB
__device__ __align__(16) u64t  g_pp [NB * NPAIR * 16];   // poses i-paired: [b][IP][k], 8 MB
__device__ __align__(16) float g_part[NCHUNK * PSLAB];   // 4 MB partials: [chunk][b][o][16]
__device__ __align__(16) float g_part2[8 * EL];          // 512 KB stage-2 partials
__device__ __align__(16) float g_v[EL];                  // v for logits this pass
__device__ __align__(16) float g_vsum[EL];               // running sum of v's

// ---------------------------------------------------------------------------
// Prep (one launch): blocks [0,4096) build g_wt2, blocks [4096,8192) build g_pp.
// g_wt2[(IP*16+k)*32+o] = pack(w[o][2IP][k], w[o][2IP+1][k]),  k = y*4+z
// g_pp [(b*NPAIR+IP)*16+k] = pack(P[b][2IP][k], P[b][2IP+1][k]), k = x*4+y
// ---------------------------------------------------------------------------
__global__ __launch_bounds__(256) void prep_kernel(const float* __restrict__ poses,
                                                   const float* __restrict__ w)
{
    int bid = blockIdx.x;
    int tid = threadIdx.x;
    if (bid < 4096) {
        int idx = bid * 256 + tid;                // (IP*16 + k)*32 + o
        int o  = idx & 31;
        int k  = (idx >> 5) & 15;
        int ip = idx >> 9;
        const float* s0 = w + ((size_t)o * NI + 2 * ip) * 16 + k;
        g_wt2[idx] = pack2(__ldg(s0), __ldg(s0 + 16));
    } else {
        int idx = (bid - 4096) * 256 + tid;       // (b*NPAIR + IP)*16 + k
        int k  = idx & 15;
        int ip = (idx >> 4) & (NPAIR - 1);
        int b  = idx >> 15;
        const float* s0 = poses + ((size_t)b * NI + 2 * ip) * 16 + k;
        g_pp[idx] = pack2(__ldg(s0), __ldg(s0 + 16));
    }
}

// ---------------------------------------------------------------------------
// pass1: warp owns (chunk c, batches b0, b0+1): lane = o, loops CP pairs.
// Each Wk load serves TWO batches -> W L1 traffic halved vs 1-batch.
// ---------------------------------------------------------------------------
__global__ __launch_bounds__(128, 4) void pass1_kernel()
{
    __shared__ __align__(16) u64t Ps[4][2][CP * 16];   // 32 KB
    const int lane = threadIdx.x & 31;
    const int warp = threadIdx.x >> 5;
    const int c    = blockIdx.x;
    const int b0   = (blockIdx.y * 4 + warp) * 2;
    const int o    = lane;

    // stage paired poses for both batches (CP*16 = 512 u64 each)
    {
        const u64t* s0 = g_pp + ((size_t)b0       * NPAIR + (size_t)c * CP) * 16;
        const u64t* s1 = g_pp + ((size_t)(b0 + 1) * NPAIR + (size_t)c * CP) * 16;
        #pragma unroll
        for (int j = 0; j < 16; j++) {
            Ps[warp][0][lane + 32 * j] = __ldg(s0 + lane + 32 * j);
            Ps[warp][1][lane + 32 * j] = __ldg(s1 + lane + 32 * j);
        }
    }
    __syncwarp();

    u64t sacc0[16], sacc1[16];
    #pragma unroll
    for (int k = 0; k < 16; k++) { sacc0[k] = 0ull; sacc1[k] = 0ull; }

    const u64t* Wb = (const u64t*)g_wt2 + (size_t)c * CP * 16 * 32 + o;

    #pragma unroll 1
    for (int ip = 0; ip < CP; ip++) {
        u64t Wk[16];
        #pragma unroll
        for (int k = 0; k < 16; k++) Wk[k] = __ldg(Wb + (ip * 16 + k) * 32);

        const u64t* P0 = &Ps[warp][0][ip * 16];
        const u64t* P1 = &Ps[warp][1][ip * 16];

        #pragma unroll
        for (int y = 0; y < 4; y++)
            #pragma unroll
            for (int x = 0; x < 4; x++) {
                u64t p0 = P0[x * 4 + y];
                u64t p1 = P1[x * 4 + y];
                #pragma unroll
                for (int z = 0; z < 4; z++) {
                    sacc0[x * 4 + z] = fma2_(p0, Wk[y * 4 + z], sacc0[x * 4 + z]);
                    sacc1[x * 4 + z] = fma2_(p1, Wk[y * 4 + z], sacc1[x * 4 + z]);
                }
            }
    }

    #pragma unroll
    for (int bb = 0; bb < 2; bb++) {
        u64t* sa = bb ? sacc1 : sacc0;
        float4* gp = (float4*)(g_part + (((size_t)c * NB + (b0 + bb)) * NO + o) * 16);
        #pragma unroll
        for (int x = 0; x < 4; x++) {
            float2 a0 = unpack2(sa[x * 4 + 0]);
            float2 a1 = unpack2(sa[x * 4 + 1]);
            float2 a2 = unpack2(sa[x * 4 + 2]);
            float2 a3 = unpack2(sa[x * 4 + 3]);
            gp[x] = make_float4(a0.x + a0.y, a1.x + a1.y, a2.x + a2.y, a3.x + a3.y);
        }
    }
}

// ---------------------------------------------------------------------------
// pass2/3: warp owns (batch b, chunk c); lane = o. vd = scalar f32 in smem
// (16 LDS.32/ip, not LDS.64); the logit dot runs scalar FFMA on the free
// register halves of the packed votes. ~110 regs, no spills at 128 cap.
// ---------------------------------------------------------------------------
__global__ __launch_bounds__(128, 4) void pass23_kernel()
{
    __shared__ __align__(16) u64t Ps[4][CP * 16];   // 16 KB
    __shared__ float Vd[4][16 * 32];                // 8 KB, [warp][k][o]
    const int lane = threadIdx.x & 31;
    const int warp = threadIdx.x >> 5;
    const int c    = blockIdx.x;
    const int b    = blockIdx.y * 4 + warp;
    const int o    = lane;

    u64t* PsW  = Ps[warp];
    float* VdW = Vd[warp];

    {
        const u64t* src = g_pp + ((size_t)b * NPAIR + (size_t)c * CP) * 16;
        #pragma unroll
        for (int j = 0; j < 16; j++) PsW[lane + 32 * j] = __ldg(src + lane + 32 * j);
    }
    {
        const float4* gv4 = (const float4*)(g_v + ((size_t)b * NO + o) * 16);
        #pragma unroll
        for (int q = 0; q < 4; q++) {
            float4 a = __ldg(gv4 + q);
            VdW[(4 * q + 0) * 32 + o] = a.x;
            VdW[(4 * q + 1) * 32 + o] = a.y;
            VdW[(4 * q + 2) * 32 + o] = a.z;
            VdW[(4 * q + 3) * 32 + o] = a.w;
        }
    }
    __syncwarp();

    u64t sacc[16];
    #pragma unroll
    for (int k = 0; k < 16; k++) sacc[k] = 0ull;

    const u64t* Wb = (const u64t*)g_wt2 + (size_t)c * CP * 16 * 32 + o;

    #pragma unroll 1
    for (int ip = 0; ip < CP; ip++) {
        u64t Wk[16];
        #pragma unroll
        for (int k = 0; k < 16; k++) Wk[k] = __ldg(Wb + (ip * 16 + k) * 32);

        const u64t* Pp = PsW + ip * 16;

        // votes V[x*4+z] halves = (V_i0, V_i1)
        u64t V[16];
        #pragma unroll
        for (int x = 0; x < 4; x++) {
            u64t p0 = Pp[x * 4];
            #pragma unroll
            for (int z = 0; z < 4; z++) V[x * 4 + z] = mul2_(p0, Wk[z]);
        }
        #pragma unroll
        for (int y = 1; y < 4; y++)
            #pragma unroll
            for (int x = 0; x < 4; x++) {
                u64t p = Pp[x * 4 + y];
                #pragma unroll
                for (int z = 0; z < 4; z++)
                    V[x * 4 + z] = fma2_(p, Wk[y * 4 + z], V[x * 4 + z]);
            }

        // logits: scalar FFMA on packed halves; vd via LDS.32 (half traffic)
        float d0 = 0.f, d1 = 0.f;
        #pragma unroll
        for (int k = 0; k < 16; k++) {
            float vf = VdW[k * 32 + o];
            float2 vv = unpack2(V[k]);
            d0 = fmaf(vv.x, vf, d0);
            d1 = fmaf(vv.y, vf, d1);
        }

        // two independent softmaxes over o (= lanes), interleaved for ILP
        float e0 = __expf(d0), e1 = __expf(d1);
        float s0 = e0, s1 = e1;
        #pragma unroll
        for (int sh = 16; sh > 0; sh >>= 1) {
            s0 += __shfl_xor_sync(0xffffffffu, s0, sh);
            s1 += __shfl_xor_sync(0xffffffffu, s1, sh);
        }
        u64t cp = pack2(__fdividef(e0, s0), __fdividef(e1, s1));

        #pragma unroll
        for (int k = 0; k < 16; k++) sacc[k] = fma2_(cp, V[k], sacc[k]);
    }

    float4* gp = (float4*)(g_part + (((size_t)c * NB + b) * NO + o) * 16);
    #pragma unroll
    for (int x = 0; x < 4; x++) {
        float2 a0 = unpack2(sacc[x * 4 + 0]);
        float2 a1 = unpack2(sacc[x * 4 + 1]);
        float2 a2 = unpack2(sacc[x * 4 + 2]);
        float2 a3 = unpack2(sacc[x * 4 + 3]);
        gp[x] = make_float4(a0.x + a0.y, a1.x + a1.y, a2.x + a2.y, a3.x + a3.y);
    }
}

// ---------------------------------------------------------------------------
// rsA: reduce 64 slabs -> 8 partials per element. 131072 threads, 8 loads
// each, fully coalesced.
// ---------------------------------------------------------------------------
__global__ __launch_bounds__(256) void rsA_kernel()
{
    int idx = blockIdx.x * 256 + threadIdx.x;   // 0 .. 8*EL-1
    int p = idx >> 14;                          // partial group 0..7
    int t = idx & (EL - 1);                     // element
    float s = 0.f;
    const float* gp = g_part + (size_t)(p * 8) * PSLAB + t;
    #pragma unroll
    for (int j = 0; j < 8; j++) s += gp[(size_t)j * PSLAB];
    g_part2[(size_t)p * EL + t] = s;
}

// ---------------------------------------------------------------------------
// rsB: reduce 8 partials + squash. 16384 threads; 16 lanes = one (b,o).
// PHASE 0: v0 -> g_v, g_vsum.  PHASE 1: g_v = v0 + v1.  PHASE 2: write output.
// ---------------------------------------------------------------------------
template<int PHASE>
__global__ __launch_bounds__(256) void rsB_kernel(float* __restrict__ out)
{
    int t = blockIdx.x * 256 + threadIdx.x;     // t = b*512 + o*16 + k
    float s = 0.f;
    #pragma unroll
    for (int p = 0; p < 8; p++) s += g_part2[(size_t)p * EL + t];
    if (PHASE == 0) s *= (1.0f / 32.0f);        // uniform coupling on iter 0

    float n2 = s * s;
    #pragma unroll
    for (int sh = 1; sh < 16; sh <<= 1)
        n2 += __shfl_xor_sync(0xffffffffu, n2, sh);   // sum over 16 pose elems

    float n = sqrtf(n2 + 1e-12f);
    float f = n2 / ((1.0f + n2) * n);
    float v = s * f;

    if (PHASE == 0)      { g_v[t] = v; g_vsum[t] = v; }
    else if (PHASE == 1) { g_v[t] = g_vsum[t] + v; }
    else {
        out[t] = v;                                     // capsule_poses [B,O,4,4]
        if ((t & 15) == 0)
            out[EL + (t >> 4)] = sqrtf(n2 * f * f + 1e-12f);  // activations
    }
}

extern "C" void kernel_launch(void* const* d_in, const int* in_sizes, int n_in,
                              void* d_out, int out_size)
{
    const float* poses = (const float*)d_in[0];
    // d_in[1] = input_activations — unused by the reference math
    const float* w     = (const float*)d_in[2];
    float* out = (float*)d_out;

    dim3 g1(NCHUNK, 4);    // pass1: 4 warps x 2 batches
    dim3 g23(NCHUNK, 8);   // pass23: 4 warps x 1 batch

    prep_kernel<<<8192, 256>>>(poses, w);

    pass1_kernel<<<g1, 128>>>();
    rsA_kernel<<<8 * EL / 256, 256>>>();
    rsB_kernel<0><<<EL / 256, 256>>>(nullptr);

    pass23_kernel<<<g23, 128>>>();
    rsA_kernel<<<8 * EL / 256, 256>>>();
    rsB_kernel<1><<<EL / 256, 256>>>(nullptr);

    pass23_kernel<<<g23, 128>>>();
    rsA_kernel<<<8 * EL / 256, 256>>>();
    rsB_kernel<2><<<EL / 256, 256>>>(out);
}

// round 16
// speedup vs baseline: 1.5875x; 1.5875x over previous
#include <cuda_runtime.h>

typedef unsigned long long u64t;

// ---- packed f32x2 helpers (sm_103a) ----
__device__ __forceinline__ u64t pack2(float x, float y){
    u64t r; asm("mov.b64 %0,{%1,%2};" : "=l"(r) : "f"(x), "f"(y)); return r;
}
__device__ __forceinline__ float2 unpack2(u64t a){
    float2 r; asm("mov.b64 {%0,%1},%2;" : "=f"(r.x), "=f"(r.y) : "l"(a)); return r;
}
__device__ __forceinline__ u64t fma2_(u64t a, u64t b, u64t c){
    u64t d; asm("fma.rn.f32x2 %0,%1,%2,%3;" : "=l"(d) : "l"(a), "l"(b), "l"(c)); return d;
}
__device__ __forceinline__ u64t mul2_(u64t a, u64t b){
    u64t d; asm("mul.rn.f32x2 %0,%1,%2;" : "=l"(d) : "l"(a), "l"(b)); return d;
}

#define NB     32                 // batches
#define NI     4096               // input capsules
#define NO     32                 // output capsules
#define NPAIR  (NI / 2)           // 2048 capsule pairs
#define CI     32                 // i per chunk
#define CP     (CI / 2)           // 16 pairs per chunk
#define NCHUNK (NI / CI)          // 128
#define EL     (NB * NO * 16)     // 16384 output elements
#define PSLAB  EL                 // floats per partial slab

// scratch (static device globals — no allocations)
__device__ __align__(16) u64t  g_wt2[NPAIR * 16 * NO];   // W i-paired: [IP][k][o], 8 MB
__device__ __align__(16) u64t  g_pp [NB * NPAIR * 16];   // poses i-paired: [b][IP][k], 8 MB
__device__ __align__(16) float g_part[NCHUNK * PSLAB];   // 8 MB partials: [chunk][b][o][16]
__device__ __align__(16) float g_part2[8 * EL];          // 512 KB stage-2 partials
__device__ __align__(16) float g_v[EL];                  // v for logits this pass
__device__ __align__(16) float g_vsum[EL];               // running sum of v's

// ---------------------------------------------------------------------------
// Prep (one launch): blocks [0,4096) build g_wt2, blocks [4096,8192) build g_pp.
// g_wt2[(IP*16+k)*32+o] = pack(w[o][2IP][k], w[o][2IP+1][k]),  k = y*4+z
// g_pp [(b*NPAIR+IP)*16+k] = pack(P[b][2IP][k], P[b][2IP+1][k]), k = x*4+y
// ---------------------------------------------------------------------------
__global__ __launch_bounds__(256) void prep_kernel(const float* __restrict__ poses,
                                                   const float* __restrict__ w)
{
    int bid = blockIdx.x;
    int tid = threadIdx.x;
    if (bid < 4096) {
        int idx = bid * 256 + tid;                // (IP*16 + k)*32 + o
        int o  = idx & 31;
        int k  = (idx >> 5) & 15;
        int ip = idx >> 9;
        const float* s0 = w + ((size_t)o * NI + 2 * ip) * 16 + k;
        g_wt2[idx] = pack2(__ldg(s0), __ldg(s0 + 16));
    } else {
        int idx = (bid - 4096) * 256 + tid;       // (b*NPAIR + IP)*16 + k
        int k  = idx & 15;
        int ip = (idx >> 4) & (NPAIR - 1);
        int b  = idx >> 15;
        const float* s0 = poses + ((size_t)b * NI + 2 * ip) * 16 + k;
        g_pp[idx] = pack2(__ldg(s0), __ldg(s0 + 16));
    }
}

// ---------------------------------------------------------------------------
// pass1 (R9-proven): warp owns (batch b, chunk c): lane = o, loops CP pairs.
// ---------------------------------------------------------------------------
__global__ __launch_bounds__(128, 4) void pass1_kernel()
{
    __shared__ __align__(16) u64t Ps[4][CP * 16];   // 8 KB, warp-private slices
    const int lane = threadIdx.x & 31;
    const int warp = threadIdx.x >> 5;
    const int c    = blockIdx.x;
    const int b    = blockIdx.y * 4 + warp;
    const int o    = lane;

    u64t* PsW = Ps[warp];
    {
        const u64t* src = g_pp + ((size_t)b * NPAIR + (size_t)c * CP) * 16;
        #pragma unroll
        for (int j = 0; j < 8; j++) PsW[lane + 32 * j] = __ldg(src + lane + 32 * j);
    }
    __syncwarp();

    u64t sacc[16];
    #pragma unroll
    for (int k = 0; k < 16; k++) sacc[k] = 0ull;

    const u64t* Wb = (const u64t*)g_wt2 + (size_t)c * CP * 16 * 32 + o;

    #pragma unroll 1
    for (int ip = 0; ip < CP; ip++) {
        u64t Wk[16];
        #pragma unroll
        for (int k = 0; k < 16; k++) Wk[k] = __ldg(Wb + (ip * 16 + k) * 32);

        const u64t* Pp = PsW + ip * 16;
        #pragma unroll
        for (int y = 0; y < 4; y++)
            #pragma unroll
            for (int x = 0; x < 4; x++) {
                u64t p = Pp[x * 4 + y];
                #pragma unroll
                for (int z = 0; z < 4; z++)
                    sacc[x * 4 + z] = fma2_(p, Wk[y * 4 + z], sacc[x * 4 + z]);
            }
    }

    float4* gp = (float4*)(g_part + (((size_t)c * NB + b) * NO + o) * 16);
    #pragma unroll
    for (int x = 0; x < 4; x++) {
        float2 a0 = unpack2(sacc[x * 4 + 0]);
        float2 a1 = unpack2(sacc[x * 4 + 1]);
        float2 a2 = unpack2(sacc[x * 4 + 2]);
        float2 a3 = unpack2(sacc[x * 4 + 3]);
        gp[x] = make_float4(a0.x + a0.y, a1.x + a1.y, a2.x + a2.y, a3.x + a3.y);
    }
}

// ---------------------------------------------------------------------------
// pass2/3: R9 body with ONE change — vd is scalar f32 in smem (16 LDS.32/ip
// instead of 16 LDS.64), logit dot via scalar FFMA on free register halves.
// Cuts pass23 L1 wavefronts ~20%; regs ~110, no spills at 128 cap.
// ---------------------------------------------------------------------------
__global__ __launch_bounds__(128, 4) void pass23_kernel()
{
    __shared__ __align__(16) u64t Ps[4][CP * 16];   // 8 KB
    __shared__ float Vd[4][16 * 32];                // 8 KB, [warp][k][o] f32
    const int lane = threadIdx.x & 31;
    const int warp = threadIdx.x >> 5;
    const int c    = blockIdx.x;
    const int b    = blockIdx.y * 4 + warp;
    const int o    = lane;

    u64t* PsW  = Ps[warp];
    float* VdW = Vd[warp];

    {
        const u64t* src = g_pp + ((size_t)b * NPAIR + (size_t)c * CP) * 16;
        #pragma unroll
        for (int j = 0; j < 8; j++) PsW[lane + 32 * j] = __ldg(src + lane + 32 * j);
    }
    {
        const float4* gv4 = (const float4*)(g_v + ((size_t)b * NO + o) * 16);
        #pragma unroll
        for (int q = 0; q < 4; q++) {
            float4 a = __ldg(gv4 + q);
            VdW[(4 * q + 0) * 32 + o] = a.x;
            VdW[(4 * q + 1) * 32 + o] = a.y;
            VdW[(4 * q + 2) * 32 + o] = a.z;
            VdW[(4 * q + 3) * 32 + o] = a.w;
        }
    }
    __syncwarp();

    u64t sacc[16];
    #pragma unroll
    for (int k = 0; k < 16; k++) sacc[k] = 0ull;

    const u64t* Wb = (const u64t*)g_wt2 + (size_t)c * CP * 16 * 32 + o;

    #pragma unroll 1
    for (int ip = 0; ip < CP; ip++) {
        u64t Wk[16];
        #pragma unroll
        for (int k = 0; k < 16; k++) Wk[k] = __ldg(Wb + (ip * 16 + k) * 32);

        const u64t* Pp = PsW + ip * 16;

        // votes V[x*4+z] halves = (V_i0, V_i1)
        u64t V[16];
        #pragma unroll
        for (int x = 0; x < 4; x++) {
            u64t p0 = Pp[x * 4];
            #pragma unroll
            for (int z = 0; z < 4; z++) V[x * 4 + z] = mul2_(p0, Wk[z]);
        }
        #pragma unroll
        for (int y = 1; y < 4; y++)
            #pragma unroll
            for (int x = 0; x < 4; x++) {
                u64t p = Pp[x * 4 + y];
                #pragma unroll
                for (int z = 0; z < 4; z++)
                    V[x * 4 + z] = fma2_(p, Wk[y * 4 + z], V[x * 4 + z]);
            }

        // logits: scalar FFMA on packed halves; vd via LDS.32 (half traffic)
        float d0 = 0.f, d1 = 0.f;
        #pragma unroll
        for (int k = 0; k < 16; k++) {
            float vf = VdW[k * 32 + o];
            float2 vv = unpack2(V[k]);
            d0 = fmaf(vv.x, vf, d0);
            d1 = fmaf(vv.y, vf, d1);
        }

        // two independent softmaxes over o (= lanes), interleaved for ILP
        float e0 = __expf(d0), e1 = __expf(d1);
        float s0 = e0, s1 = e1;
        #pragma unroll
        for (int sh = 16; sh > 0; sh >>= 1) {
            s0 += __shfl_xor_sync(0xffffffffu, s0, sh);
            s1 += __shfl_xor_sync(0xffffffffu, s1, sh);
        }
        u64t cp = pack2(__fdividef(e0, s0), __fdividef(e1, s1));

        #pragma unroll
        for (int k = 0; k < 16; k++) sacc[k] = fma2_(cp, V[k], sacc[k]);
    }

    float4* gp = (float4*)(g_part + (((size_t)c * NB + b) * NO + o) * 16);
    #pragma unroll
    for (int x = 0; x < 4; x++) {
        float2 a0 = unpack2(sacc[x * 4 + 0]);
        float2 a1 = unpack2(sacc[x * 4 + 1]);
        float2 a2 = unpack2(sacc[x * 4 + 2]);
        float2 a3 = unpack2(sacc[x * 4 + 3]);
        gp[x] = make_float4(a0.x + a0.y, a1.x + a1.y, a2.x + a2.y, a3.x + a3.y);
    }
}

// ---------------------------------------------------------------------------
// rsA: reduce 128 slabs -> 8 partials per element. 131072 threads, coalesced.
// ---------------------------------------------------------------------------
__global__ __launch_bounds__(256) void rsA_kernel()
{
    int idx = blockIdx.x * 256 + threadIdx.x;   // 0 .. 8*EL-1
    int p = idx >> 14;                          // partial group 0..7
    int t = idx & (EL - 1);                     // element
    float s = 0.f;
    const float* gp = g_part + (size_t)(p * 16) * PSLAB + t;
    #pragma unroll
    for (int j = 0; j < 16; j++) s += gp[(size_t)j * PSLAB];
    g_part2[(size_t)p * EL + t] = s;
}

// ---------------------------------------------------------------------------
// rsB: reduce 8 partials + squash. 16384 threads; 16 lanes = one (b,o).
// PHASE 0: v0 -> g_v, g_vsum.  PHASE 1: g_v = v0 + v1.  PHASE 2: write output.
// ---------------------------------------------------------------------------
template<int PHASE>
__global__ __launch_bounds__(256) void rsB_kernel(float* __restrict__ out)
{
    int t = blockIdx.x * 256 + threadIdx.x;     // t = b*512 + o*16 + k
    float s = 0.f;
    #pragma unroll
    for (int p = 0; p < 8; p++) s += g_part2[(size_t)p * EL + t];
    if (PHASE == 0) s *= (1.0f / 32.0f);        // uniform coupling on iter 0

    float n2 = s * s;
    #pragma unroll
    for (int sh = 1; sh < 16; sh <<= 1)
        n2 += __shfl_xor_sync(0xffffffffu, n2, sh);   // sum over 16 pose elems

    float n = sqrtf(n2 + 1e-12f);
    float f = n2 / ((1.0f + n2) * n);
    float v = s * f;

    if (PHASE == 0)      { g_v[t] = v; g_vsum[t] = v; }
    else if (PHASE == 1) { g_v[t] = g_vsum[t] + v; }
    else {
        out[t] = v;                                     // capsule_poses [B,O,4,4]
        if ((t & 15) == 0)
            out[EL + (t >> 4)] = sqrtf(n2 * f * f + 1e-12f);  // activations
    }
}

extern "C" void kernel_launch(void* const* d_in, const int* in_sizes, int n_in,
                              void* d_out, int out_size)
{
    const float* poses = (const float*)d_in[0];
    // d_in[1] = input_activations — unused by the reference math
    const float* w     = (const float*)d_in[2];
    float* out = (float*)d_out;

    dim3 pgrid(NCHUNK, NB / 4);   // 128 x 8 blocks of 128 threads

    prep_kernel<<<8192, 256>>>(poses, w);

    pass1_kernel<<<pgrid, 128>>>();
    rsA_kernel<<<8 * EL / 256, 256>>>();
    rsB_kernel<0><<<EL / 256, 256>>>(nullptr);

    pass23_kernel<<<pgrid, 128>>>();
    rsA_kernel<<<8 * EL / 256, 256>>>();
    rsB_kernel<1><<<EL / 256, 256>>>(nullptr);

    pass23_kernel<<<pgrid, 128>>>();
    rsA_kernel<<<8 * EL / 256, 256>>>();
    rsB_kernel<2><<<EL / 256, 256>>>(out);
}